// round 4
// baseline (speedup 1.0000x reference)
#include <cuda_runtime.h>

typedef unsigned long long u64;

// ---------------------------------------------------------------------------
// QuanvolutionFilter reformulated:
//   out_k(patch) = sum_{ia,ib} C_k[ia,ib] * p01[ia] * p23[ib],
//   p01/p23 = (1,cos,sin) tensor factors of wire pairs (0,1) and (2,3).
// C precomputed on-device; stored DUPLICATED per 32-bit half so the main
// kernel can pack TWO PATCHES per f32x2 lane pair (no splats needed).
// ---------------------------------------------------------------------------

__device__ __align__(16) u64 g_Cd[324]; // [t][k], each u64 = {C,C} duplicated

struct cplx { float x, y; };

#define NW 4
#define NL 3

__global__ void setup_kernel(const float* __restrict__ params,
                             const float* __restrict__ W,
                             const float* __restrict__ bias) {
    __shared__ float G[12][8];        // per-gate 2x2 complex coeffs
    __shared__ cplx U[16][16];        // U[row][col]
    __shared__ float A[4 * 256];      // A[k][i][j]
    __shared__ float zwk[4][16];
    int tid = threadIdx.x;            // 256 threads

    // Precompute all 12 Rot gate coefficient sets in parallel (full precision)
    if (tid < 12) {
        float phi = params[tid * 3 + 0];
        float th  = params[tid * 3 + 1];
        float om  = params[tid * 3 + 2];
        float ch = cosf(0.5f * th), sh = sinf(0.5f * th);
        float al = 0.5f * (phi + om), be = 0.5f * (phi - om);
        float ca = cosf(al), sa = sinf(al);
        float cb = cosf(be), sb = sinf(be);
        G[tid][0] =  ch * ca; G[tid][1] = -ch * sa;   // g00
        G[tid][2] = -sh * cb; G[tid][3] = -sh * sb;   // g01
        G[tid][4] =  sh * cb; G[tid][5] = -sh * sb;   // g10
        G[tid][6] =  ch * ca; G[tid][7] =  ch * sa;   // g11
    }
    // U = I
    { int r = tid >> 4, c = tid & 15; U[r][c] = { (r == c) ? 1.f : 0.f, 0.f }; }
    // zwk[k][b] = sum_w W[k,w] * (1 - 2*bit_w(b))  (parallel with gate calc)
    if (tid >= 128 && tid < 192) {
        int k = (tid - 128) >> 4, bb = tid & 15;
        float s = 0.f;
        #pragma unroll
        for (int w = 0; w < NW; w++) {
            float z = ((bb >> (3 - w)) & 1) ? -1.f : 1.f;
            s += W[k * 4 + w] * z;
        }
        zwk[k][bb] = s;
    }
    __syncthreads();

    for (int l = 0; l < NL; l++) {
        for (int w = 0; w < NW; w++) {
            if (tid < 128) {
                const float* g = G[l * 4 + w];
                float g00r = g[0], g00i = g[1], g01r = g[2], g01i = g[3];
                float g10r = g[4], g10i = g[5], g11r = g[6], g11i = g[7];
                int pos = 3 - w, m = 1 << pos;
                int col = tid & 15, pidx = tid >> 4;
                int low  = pidx & (m - 1);
                int high = pidx >> pos;
                int i = (high << (pos + 1)) | low;
                int j = i | m;
                cplx ui = U[i][col], uj = U[j][col];
                U[i][col] = { g00r * ui.x - g00i * ui.y + g01r * uj.x - g01i * uj.y,
                              g00r * ui.y + g00i * ui.x + g01r * uj.y + g01i * uj.x };
                U[j][col] = { g10r * ui.x - g10i * ui.y + g11r * uj.x - g11i * uj.y,
                              g10r * ui.y + g10i * ui.x + g11r * uj.y + g11i * uj.x };
            }
            __syncthreads();
        }
        int rng = (l % (NW - 1)) + 1;
        for (int w = 0; w < NW; w++) {
            int tgt = (w + rng) % NW;
            int cm = 1 << (3 - w), tm = 1 << (3 - tgt);
            if (tid < 64) {
                int col = tid & 15, pi = tid >> 4;
                int cnt = -1, row = 0;
                for (int r2 = 0; r2 < 16; r2++) {
                    if ((r2 & cm) && !(r2 & tm)) {
                        cnt++;
                        if (cnt == pi) { row = r2; break; }
                    }
                }
                int j = row | tm;
                cplx t0 = U[row][col], t1 = U[j][col];
                U[row][col] = t1;
                U[j][col]   = t0;
            }
            __syncthreads();
        }
    }

    // A[k][i][j] = sum_b zwk[k][b] * Re( conj(U[b][i]) * U[b][j] )
    for (int idx = tid; idx < 1024; idx += 256) {
        int k = idx >> 8, ij = idx & 255, i = ij >> 4, j = ij & 15;
        float s = 0.f;
        #pragma unroll
        for (int bb = 0; bb < 16; bb++) {
            float re = U[bb][i].x * U[bb][j].x + U[bb][i].y * U[bb][j].y;
            s += zwk[k][bb] * re;
        }
        A[idx] = s;
    }
    __syncthreads();

    // Basis change to (1,cos,sin)^{x4}; factor 1/16, bias in constant term.
    for (int idx = tid; idx < 324; idx += 256) {
        int t_idx = idx >> 2, k = idx & 3;
        int tw[4];
        tw[3] = t_idx % 3;
        tw[2] = (t_idx / 3) % 3;
        tw[1] = (t_idx / 9) % 3;
        tw[0] = t_idx / 27;
        float sum = 0.f;
        for (int combo = 0; combo < 16; combo++) {
            int i = 0, j = 0;
            float sign = 1.f;
            #pragma unroll
            for (int w = 0; w < 4; w++) {
                int c = (combo >> w) & 1;
                int t = tw[w];
                int iw, jw;
                if (t == 0)      { iw = c; jw = c; }
                else if (t == 1) { iw = c; jw = c; if (c) sign = -sign; }
                else             { iw = c; jw = 1 - c; }
                i |= iw << (3 - w);
                j |= jw << (3 - w);
            }
            sum += sign * A[k * 256 + i * 16 + j];
        }
        float val = sum * (1.f / 16.f);
        if (t_idx == 0) val += bias[k];
        unsigned int vi = __float_as_uint(val);
        g_Cd[t_idx * 4 + k] = (u64)vi | ((u64)vi << 32);
    }
}

// --------------------------- main kernel -----------------------------------

__device__ __forceinline__ u64 pack2(float lo, float hi) {
    u64 r;
    asm("mov.b64 %0, {%1, %2};" : "=l"(r)
        : "r"(__float_as_uint(lo)), "r"(__float_as_uint(hi)));
    return r;
}
__device__ __forceinline__ u64 mul2(u64 a, u64 b) {
    u64 r; asm("mul.rn.f32x2 %0, %1, %2;" : "=l"(r) : "l"(a), "l"(b)); return r;
}
__device__ __forceinline__ u64 fma2(u64 a, u64 b, u64 c) {
    u64 r; asm("fma.rn.f32x2 %0, %1, %2, %3;" : "=l"(r) : "l"(a), "l"(b), "l"(c));
    return r;
}

// 4 patches per thread = 2 f32x2 groups; coefficients duplicated in shared.
__global__ void __launch_bounds__(256) quanv_kernel(const float* __restrict__ x,
                                                    float* __restrict__ out,
                                                    int quarter) {
    __shared__ __align__(16) u64 Cs[324];   // [t][k] duplicated
    {
        const ulonglong2* src = (const ulonglong2*)g_Cd;
        ulonglong2* dst = (ulonglong2*)Cs;
        for (int i = threadIdx.x; i < 162; i += 256) dst[i] = src[i];
    }
    __syncthreads();

    int t = blockIdx.x * 256 + threadIdx.x;
    if (t >= quarter) return;

    u64 w0c[2], w0s[2], w1c[2], w1s[2];  // wires 0,1 trig packs per group
    u64 p23[2][9];                        // wires 2,3 tensor factors per group

    #pragma unroll
    for (int g = 0; g < 2; g++) {
        float cA[4], sA[4], cB[4], sB[4];
        {
            int p  = t + (2 * g) * quarter;
            int b  = p / 196, q = p - b * 196;
            int py = q / 14,  px = q - py * 14;
            const float* base = x + b * 784 + py * 56 + px * 2;
            float2 r0 = *(const float2*)base;
            float2 r1 = *(const float2*)(base + 28);
            __sincosf(r0.x, &sA[0], &cA[0]);
            __sincosf(r0.y, &sA[1], &cA[1]);
            __sincosf(r1.x, &sA[2], &cA[2]);
            __sincosf(r1.y, &sA[3], &cA[3]);
        }
        {
            int p  = t + (2 * g + 1) * quarter;
            int b  = p / 196, q = p - b * 196;
            int py = q / 14,  px = q - py * 14;
            const float* base = x + b * 784 + py * 56 + px * 2;
            float2 r0 = *(const float2*)base;
            float2 r1 = *(const float2*)(base + 28);
            __sincosf(r0.x, &sB[0], &cB[0]);
            __sincosf(r0.y, &sB[1], &cB[1]);
            __sincosf(r1.x, &sB[2], &cB[2]);
            __sincosf(r1.y, &sB[3], &cB[3]);
        }
        w0c[g] = pack2(cA[0], cB[0]); w0s[g] = pack2(sA[0], sB[0]);
        w1c[g] = pack2(cA[1], cB[1]); w1s[g] = pack2(sA[1], sB[1]);
        u64 c2p = pack2(cA[2], cB[2]), s2p = pack2(sA[2], sB[2]);
        u64 c3p = pack2(cA[3], cB[3]), s3p = pack2(sA[3], sB[3]);
        p23[g][0] = 0; // unused (factor == 1)
        p23[g][1] = c3p;            p23[g][2] = s3p;
        p23[g][3] = c2p;            p23[g][4] = mul2(c2p, c3p);
        p23[g][5] = mul2(c2p, s3p); p23[g][6] = s2p;
        p23[g][7] = mul2(s2p, c3p); p23[g][8] = mul2(s2p, s3p);
    }

    u64 acc[2][4];

    #pragma unroll
    for (int ia = 0; ia < 9; ia++) {
        // m[g][k] = sum_ib C_k[ia,ib] * p23[g][ib];   ib=0 term is just C.
        u64 m[2][4];
        {
            const ulonglong2* Cp = (const ulonglong2*)&Cs[(ia * 9) * 4];
            ulonglong2 c01 = Cp[0], c23 = Cp[1];
            #pragma unroll
            for (int g = 0; g < 2; g++) {
                m[g][0] = c01.x; m[g][1] = c01.y;
                m[g][2] = c23.x; m[g][3] = c23.y;
            }
        }
        #pragma unroll
        for (int ib = 1; ib < 9; ib++) {
            const ulonglong2* Cp = (const ulonglong2*)&Cs[(ia * 9 + ib) * 4];
            ulonglong2 c01 = Cp[0], c23 = Cp[1];
            #pragma unroll
            for (int g = 0; g < 2; g++) {
                m[g][0] = fma2(c01.x, p23[g][ib], m[g][0]);
                m[g][1] = fma2(c01.y, p23[g][ib], m[g][1]);
                m[g][2] = fma2(c23.x, p23[g][ib], m[g][2]);
                m[g][3] = fma2(c23.y, p23[g][ib], m[g][3]);
            }
        }
        // acc += p01[ia] * m;  p01 factor from {1,c0,s0} x {1,c1,s1}
        const int t0 = ia / 3, t1 = ia % 3;
        if (ia == 0) {
            #pragma unroll
            for (int g = 0; g < 2; g++)
                #pragma unroll
                for (int k = 0; k < 4; k++) acc[g][k] = m[g][k];
        } else {
            #pragma unroll
            for (int g = 0; g < 2; g++) {
                u64 pa;
                if (t0 == 0)      pa = (t1 == 1) ? w1c[g] : w1s[g];
                else if (t1 == 0) pa = (t0 == 1) ? w0c[g] : w0s[g];
                else              pa = mul2((t0 == 1) ? w0c[g] : w0s[g],
                                            (t1 == 1) ? w1c[g] : w1s[g]);
                #pragma unroll
                for (int k = 0; k < 4; k++)
                    acc[g][k] = fma2(pa, m[g][k], acc[g][k]);
            }
        }
    }

    #pragma unroll
    for (int g = 0; g < 2; g++) {
        unsigned int lo[4], hi[4];
        #pragma unroll
        for (int k = 0; k < 4; k++)
            asm("mov.b64 {%0, %1}, %2;" : "=r"(lo[k]), "=r"(hi[k]) : "l"(acc[g][k]));
        int pA = t + (2 * g) * quarter;
        int pB = t + (2 * g + 1) * quarter;
        ((float4*)out)[pA] = make_float4(__uint_as_float(lo[0]), __uint_as_float(lo[1]),
                                         __uint_as_float(lo[2]), __uint_as_float(lo[3]));
        ((float4*)out)[pB] = make_float4(__uint_as_float(hi[0]), __uint_as_float(hi[1]),
                                         __uint_as_float(hi[2]), __uint_as_float(hi[3]));
    }
}

extern "C" void kernel_launch(void* const* d_in, const int* in_sizes, int n_in,
                              void* d_out, int out_size) {
    const float* x      = (const float*)d_in[0];
    const float* params = (const float*)d_in[1];
    const float* W      = (const float*)d_in[2];
    const float* bias   = (const float*)d_in[3];

    int nPatches = in_sizes[0] / 4;   // B*196
    int quarter  = nPatches / 4;      // exact: 196 % 4 == 0

    setup_kernel<<<1, 256>>>(params, W, bias);
    quanv_kernel<<<(quarter + 255) / 256, 256>>>(x, (float*)d_out, quarter);
}